// round 1
// baseline (speedup 1.0000x reference)
#include <cuda_runtime.h>

#define DOF 7
#define HID 30
#define TPB 256

typedef unsigned long long u64;

// ---------------------------------------------------------------------------
// Fused parameter block (all matrices pre-contracted; padded for vector loads)
// ---------------------------------------------------------------------------
struct alignas(16) Params {
    float ld_w1[HID][8];   // [h][d], pad col 7 = 0
    float lo_w1[HID][8];
    float g_w1[HID][8];
    float ld_b1[32];
    float lo_b1[32];
    float g_b1[32];
    float MA[HID][32];     // [h][j]: MA[j,h] = sum_o m_w1[j,o]*ld_w2[o,h]
    float MB[HID][32];     // lo part of m head
    float CA[HID][32];     // [h][j]: sum_{o,d} c_w1[j,7o+d]*ld_w2[o,h]*ld_w1[h,d]
    float CB[HID][32];
    float Mq[DOF][32];     // [d][j] = m_w1[j][28+d]   (qDDot path)
    float Cq[DOF][32];     // [d][j] = c_w1[j][196+d]  (qDot path)
    float mb1p[32];        // m_b1 + m_w1[:, :28] @ [ld_b2; lo_b2]
    float cb1[32];
    float w2m[HID][8];     // [j][o] transposed second layers
    float w2c[HID][8];
    float w2g[HID][8];
    float b_out[8];        // m_b2 + c_b2 + g_b2
};

__device__ Params d_params;

// ---------------------------------------------------------------------------
// Prep kernel: one block, builds all fused weights (trivial cost, ~180K FMA)
// ---------------------------------------------------------------------------
__global__ void prep_kernel(
    const float* __restrict__ ld_w1, const float* __restrict__ ld_b1,
    const float* __restrict__ ld_w2, const float* __restrict__ ld_b2,
    const float* __restrict__ lo_w1, const float* __restrict__ lo_b1,
    const float* __restrict__ lo_w2, const float* __restrict__ lo_b2,
    const float* __restrict__ g_w1,  const float* __restrict__ g_b1,
    const float* __restrict__ g_w2,  const float* __restrict__ g_b2,
    const float* __restrict__ m_w1,  const float* __restrict__ m_b1,
    const float* __restrict__ m_w2,  const float* __restrict__ m_b2,
    const float* __restrict__ c_w1,  const float* __restrict__ c_b1,
    const float* __restrict__ c_w2,  const float* __restrict__ c_b2)
{
    const int t = threadIdx.x;
    float* P = reinterpret_cast<float*>(&d_params);
    for (int i = t; i < (int)(sizeof(Params) / 4); i += blockDim.x) P[i] = 0.f;
    __syncthreads();

    // first-layer weights (padded rows) + transposed second layers
    for (int i = t; i < HID * DOF; i += blockDim.x) {
        int h = i / DOF, d = i % DOF;
        d_params.ld_w1[h][d] = ld_w1[i];
        d_params.lo_w1[h][d] = lo_w1[i];
        d_params.g_w1[h][d]  = g_w1[i];
        int j = i / DOF, o = i % DOF;           // reuse index split as (j,o)
        d_params.w2m[j][o] = m_w2[o * HID + j];
        d_params.w2c[j][o] = c_w2[o * HID + j];
        d_params.w2g[j][o] = g_w2[o * HID + j];
    }
    // biases; mb1p absorbs the ld_b2/lo_b2 contributions into the m hidden bias
    for (int h = t; h < HID; h += blockDim.x) {
        d_params.ld_b1[h] = ld_b1[h];
        d_params.lo_b1[h] = lo_b1[h];
        d_params.g_b1[h]  = g_b1[h];
        d_params.cb1[h]   = c_b1[h];
        float v = m_b1[h];                       // h plays the role of j here
        for (int o = 0; o < DOF; o++) v += m_w1[h * 35 + o] * ld_b2[o];
        for (int o = 0; o < 21;  o++) v += m_w1[h * 35 + 7 + o] * lo_b2[o];
        d_params.mb1p[h] = v;
    }
    // direct qDot/qDDot columns
    for (int i = t; i < DOF * HID; i += blockDim.x) {
        int d = i / HID, j = i % HID;
        d_params.Mq[d][j] = m_w1[j * 35 + 28 + d];
        d_params.Cq[d][j] = c_w1[j * 203 + 196 + d];
    }
    if (t < DOF) d_params.b_out[t] = m_b2[t] + c_b2[t] + g_b2[t];

    // fused 30x30 matrices (reads only global inputs -> no intra-kernel races)
    for (int i = t; i < HID * HID; i += blockDim.x) {
        int h = i / HID, j = i % HID;
        float ma = 0.f, mb = 0.f, ca = 0.f, cb = 0.f;
        for (int o = 0; o < DOF; o++) {
            float w2 = ld_w2[o * HID + h];
            ma += m_w1[j * 35 + o] * w2;
            float s = 0.f;
            for (int d = 0; d < DOF; d++)
                s += c_w1[j * 203 + o * 7 + d] * ld_w1[h * DOF + d];
            ca += w2 * s;
        }
        for (int o = 0; o < 21; o++) {
            float w2 = lo_w2[o * HID + h];
            mb += m_w1[j * 35 + 7 + o] * w2;
            float s = 0.f;
            for (int d = 0; d < DOF; d++)
                s += c_w1[j * 203 + (7 + o) * 7 + d] * lo_w1[h * DOF + d];
            cb += w2 * s;
        }
        d_params.MA[h][j] = ma;
        d_params.MB[h][j] = mb;
        d_params.CA[h][j] = ca;
        d_params.CB[h][j] = cb;
    }
}

// ---------------------------------------------------------------------------
// Packed f32x2 helpers (FFMA2: only reachable via PTX fma.rn.f32x2)
// ---------------------------------------------------------------------------
__device__ __forceinline__ u64 ffma2(u64 a, u64 b, u64 c) {
    u64 d;
    asm("fma.rn.f32x2 %0, %1, %2, %3;" : "=l"(d) : "l"(a), "l"(b), "l"(c));
    return d;
}
__device__ __forceinline__ u64 pk2(float x) {
    u64 r;
    asm("mov.b64 %0, {%1, %2};" : "=l"(r) : "f"(x), "f"(x));
    return r;
}
__device__ __forceinline__ float2 upk(u64 v) {
    float2 f;
    asm("mov.b64 {%0, %1}, %2;" : "=f"(f.x), "=f"(f.y) : "l"(v));
    return f;
}
__device__ __forceinline__ float sigm(float z) {
    return __fdividef(1.f, 1.f + __expf(-z));
}

// z[16] pairs (30 outputs + 2 zero pads): z = bias + v @ Mv
__device__ __forceinline__ void vec_init(const float* __restrict__ bias,
                                         const float (*__restrict__ Mv)[32],
                                         const float* __restrict__ v, u64* z)
{
    const ulonglong2* b = reinterpret_cast<const ulonglong2*>(bias);
    #pragma unroll
    for (int i = 0; i < 8; i++) { ulonglong2 w = b[i]; z[2*i] = w.x; z[2*i+1] = w.y; }
    #pragma unroll
    for (int d = 0; d < DOF; d++) {
        u64 vb = pk2(v[d]);
        const ulonglong2* row = reinterpret_cast<const ulonglong2*>(&Mv[d][0]);
        #pragma unroll
        for (int i = 0; i < 8; i++) {
            ulonglong2 w = row[i];
            z[2*i]   = ffma2(vb, w.x, z[2*i]);
            z[2*i+1] = ffma2(vb, w.y, z[2*i+1]);
        }
    }
}

// z += trig(w1 @ q + b1) @ M   (COS selects cos vs sin)
template <bool COS>
__device__ __forceinline__ void hidden_accum(const float (*__restrict__ w1)[8],
                                             const float* __restrict__ b1,
                                             const float (*__restrict__ M)[32],
                                             const float* __restrict__ q, u64* z)
{
    #pragma unroll 2
    for (int h = 0; h < HID; h++) {
        const float4 wa = *reinterpret_cast<const float4*>(&w1[h][0]);
        const float4 wb = *reinterpret_cast<const float4*>(&w1[h][4]);
        float pre = b1[h];
        pre = fmaf(wa.x, q[0], pre); pre = fmaf(wa.y, q[1], pre);
        pre = fmaf(wa.z, q[2], pre); pre = fmaf(wa.w, q[3], pre);
        pre = fmaf(wb.x, q[4], pre); pre = fmaf(wb.y, q[5], pre);
        pre = fmaf(wb.z, q[6], pre);
        u64 s2 = pk2(COS ? __cosf(pre) : __sinf(pre));
        const ulonglong2* row = reinterpret_cast<const ulonglong2*>(&M[h][0]);
        #pragma unroll
        for (int i = 0; i < 8; i++) {
            ulonglong2 w = row[i];
            z[2*i]   = ffma2(s2, w.x, z[2*i]);
            z[2*i+1] = ffma2(s2, w.y, z[2*i+1]);
        }
    }
}

// acc += sigmoid(z) @ w2
__device__ __forceinline__ void sig_out(const u64* z, const float (*__restrict__ w2)[8],
                                        u64* acc)
{
    #pragma unroll 3
    for (int p = 0; p < 15; p++) {
        float2 zz = upk(z[p]);
        u64 a0 = pk2(sigm(zz.x));
        u64 a1 = pk2(sigm(zz.y));
        const ulonglong2* r0 = reinterpret_cast<const ulonglong2*>(&w2[2*p][0]);
        const ulonglong2* r1 = reinterpret_cast<const ulonglong2*>(&w2[2*p+1][0]);
        ulonglong2 w0a = r0[0], w0b = r0[1];
        ulonglong2 w1a = r1[0], w1b = r1[1];
        acc[0] = ffma2(a0, w0a.x, acc[0]); acc[1] = ffma2(a0, w0a.y, acc[1]);
        acc[2] = ffma2(a0, w0b.x, acc[2]); acc[3] = ffma2(a0, w0b.y, acc[3]);
        acc[0] = ffma2(a1, w1a.x, acc[0]); acc[1] = ffma2(a1, w1a.y, acc[1]);
        acc[2] = ffma2(a1, w1b.x, acc[2]); acc[3] = ffma2(a1, w1b.y, acc[3]);
    }
}

// ---------------------------------------------------------------------------
// Main kernel: one thread per batch element
// ---------------------------------------------------------------------------
__global__ __launch_bounds__(TPB) void delan_kernel(const float* __restrict__ x,
                                                    float* __restrict__ out, int B)
{
    __shared__ alignas(16) Params sp;
    __shared__ alignas(16) float sx[TPB * 21];   // reused as output staging at the end
    const int t = threadIdx.x;
    const long base = (long)blockIdx.x * TPB;

    // stage fused weights into shared (coalesced float4)
    {
        const float4* src = reinterpret_cast<const float4*>(&d_params);
        float4* dst = reinterpret_cast<float4*>(&sp);
        constexpr int N4 = (int)(sizeof(Params) / 16);
        for (int i = t; i < N4; i += TPB) dst[i] = src[i];
    }
    // stage this block's x rows (coalesced float4)
    {
        const float4* gx = reinterpret_cast<const float4*>(x);
        float4* sx4 = reinterpret_cast<float4*>(sx);
        const long gbase = base * 21 / 4;
        const long gtot  = (long)B * 21 / 4;
        #pragma unroll
        for (int i = 0; i < 6; i++) {
            int idx = t + i * TPB;
            if (idx < TPB * 21 / 4 && gbase + idx < gtot) sx4[idx] = gx[gbase + idx];
        }
    }
    __syncthreads();

    float q[7];
    #pragma unroll
    for (int d = 0; d < 7; d++) q[d] = sx[t * 21 + d];

    u64 acc[4];
    {
        const ulonglong2* b = reinterpret_cast<const ulonglong2*>(sp.b_out);
        ulonglong2 b0 = b[0], b1 = b[1];
        acc[0] = b0.x; acc[1] = b0.y; acc[2] = b1.x; acc[3] = b1.y;
    }

    // ---- g net: acc += sin(g_w1 q + g_b1) @ g_w2^T -------------------------
    #pragma unroll 2
    for (int h = 0; h < HID; h++) {
        const float4 wa = *reinterpret_cast<const float4*>(&sp.g_w1[h][0]);
        const float4 wb = *reinterpret_cast<const float4*>(&sp.g_w1[h][4]);
        float pre = sp.g_b1[h];
        pre = fmaf(wa.x, q[0], pre); pre = fmaf(wa.y, q[1], pre);
        pre = fmaf(wa.z, q[2], pre); pre = fmaf(wa.w, q[3], pre);
        pre = fmaf(wb.x, q[4], pre); pre = fmaf(wb.y, q[5], pre);
        pre = fmaf(wb.z, q[6], pre);
        u64 s2 = pk2(__sinf(pre));
        const ulonglong2* r = reinterpret_cast<const ulonglong2*>(&sp.w2g[h][0]);
        ulonglong2 wA = r[0], wB = r[1];
        acc[0] = ffma2(s2, wA.x, acc[0]); acc[1] = ffma2(s2, wA.y, acc[1]);
        acc[2] = ffma2(s2, wB.x, acc[2]); acc[3] = ffma2(s2, wB.y, acc[3]);
    }

    u64 z[16];

    // ---- m head: z = mb1p + qDDot@Mq + sin_ld@MA + sin_lo@MB ---------------
    {
        float v[7];
        #pragma unroll
        for (int d = 0; d < 7; d++) v[d] = sx[t * 21 + 14 + d];   // qDDot
        vec_init(sp.mb1p, sp.Mq, v, z);
    }
    hidden_accum<false>(sp.ld_w1, sp.ld_b1, sp.MA, q, z);
    hidden_accum<false>(sp.lo_w1, sp.lo_b1, sp.MB, q, z);
    sig_out(z, sp.w2m, acc);

    // ---- c head: z = c_b1 + qDot@Cq + cos_ld@CA + cos_lo@CB ----------------
    {
        float v[7];
        #pragma unroll
        for (int d = 0; d < 7; d++) v[d] = sx[t * 21 + 7 + d];    // qDot
        vec_init(sp.cb1, sp.Cq, v, z);
    }
    hidden_accum<true>(sp.ld_w1, sp.ld_b1, sp.CA, q, z);
    hidden_accum<true>(sp.lo_w1, sp.lo_b1, sp.CB, q, z);
    sig_out(z, sp.w2c, acc);

    // ---- output staging (reuse sx) + coalesced store -----------------------
    __syncthreads();                 // all sx reads done before aliasing as output
    float* so = sx;
    {
        float2 v0 = upk(acc[0]), v1 = upk(acc[1]), v2 = upk(acc[2]), v3 = upk(acc[3]);
        so[t * 7 + 0] = v0.x; so[t * 7 + 1] = v0.y;
        so[t * 7 + 2] = v1.x; so[t * 7 + 3] = v1.y;
        so[t * 7 + 4] = v2.x; so[t * 7 + 5] = v2.y;
        so[t * 7 + 6] = v3.x;
    }
    __syncthreads();
    {
        float4* go = reinterpret_cast<float4*>(out);
        const float4* so4 = reinterpret_cast<const float4*>(so);
        const long obase = base * 7 / 4;
        const long otot  = (long)B * 7 / 4;
        #pragma unroll
        for (int i = 0; i < 2; i++) {
            int idx = t + i * TPB;
            if (idx < TPB * 7 / 4 && obase + idx < otot) go[obase + idx] = so4[idx];
        }
    }
}

// ---------------------------------------------------------------------------
extern "C" void kernel_launch(void* const* d_in, const int* in_sizes, int n_in,
                              void* d_out, int out_size)
{
    const float* x = (const float*)d_in[0];
    prep_kernel<<<1, 256>>>(
        (const float*)d_in[1],  (const float*)d_in[2],  (const float*)d_in[3],  (const float*)d_in[4],
        (const float*)d_in[5],  (const float*)d_in[6],  (const float*)d_in[7],  (const float*)d_in[8],
        (const float*)d_in[9],  (const float*)d_in[10], (const float*)d_in[11], (const float*)d_in[12],
        (const float*)d_in[13], (const float*)d_in[14], (const float*)d_in[15], (const float*)d_in[16],
        (const float*)d_in[17], (const float*)d_in[18], (const float*)d_in[19], (const float*)d_in[20]);

    const int B = in_sizes[0] / (3 * DOF);
    const int nb = (B + TPB - 1) / TPB;
    delan_kernel<<<nb, TPB>>>(x, (float*)d_out, B);
}

// round 2
// speedup vs baseline: 1.4107x; 1.4107x over previous
#include <cuda_runtime.h>

#define DOF 7
#define HID 30
#define TPB 128          // threads per block
#define EPB 256          // elements per block (2 per thread)

typedef unsigned long long u64;

// ---------------------------------------------------------------------------
// Fused parameter block. w1 rows carry b1 in padding slot [7] (use q[7]=1).
// ---------------------------------------------------------------------------
struct alignas(16) Params {
    float ld_w1[HID][8];   // [h][0..6]=w, [7]=b1
    float lo_w1[HID][8];
    float g_w1[HID][8];
    float MA[HID][32];     // [h][j]: MA[j,h] = sum_o m_w1[j,o]*ld_w2[o,h]
    float MB[HID][32];
    float CA[HID][32];     // [h][j]: sum_{o,d} c_w1[j,7o+d]*ld_w2[o,h]*ld_w1[h,d]
    float CB[HID][32];
    float Mq[DOF][32];     // [d][j] = m_w1[j][28+d]   (qDDot path)
    float Cq[DOF][32];     // [d][j] = c_w1[j][196+d]  (qDot path)
    float mb1p[32];        // m_b1 + m_w1[:, :28] @ [ld_b2; lo_b2]
    float cb1[32];
    float w2m[HID][8];     // [j][o] transposed second layers, col 7 = 0
    float w2c[HID][8];
    float w2g[HID][8];
    float b_out[8];        // m_b2 + c_b2 + g_b2
};

__device__ Params d_params;

// ---------------------------------------------------------------------------
// Prep kernel 1: one block — everything except the four 30x30 fused matrices
// ---------------------------------------------------------------------------
__global__ void prep_small(
    const float* __restrict__ ld_w1, const float* __restrict__ ld_b1,
    const float* __restrict__ ld_w2, const float* __restrict__ ld_b2,
    const float* __restrict__ lo_w1, const float* __restrict__ lo_b1,
    const float* __restrict__ lo_w2, const float* __restrict__ lo_b2,
    const float* __restrict__ g_w1,  const float* __restrict__ g_b1,
    const float* __restrict__ g_w2,  const float* __restrict__ g_b2,
    const float* __restrict__ m_w1,  const float* __restrict__ m_b1,
    const float* __restrict__ m_w2,  const float* __restrict__ m_b2,
    const float* __restrict__ c_w1,  const float* __restrict__ c_b1,
    const float* __restrict__ c_w2,  const float* __restrict__ c_b2)
{
    const int t = threadIdx.x;
    // zero small regions (matrix block is fully written by prep_mats incl. pads)
    for (int h = t; h < HID; h += blockDim.x) {
        d_params.ld_w1[h][7] = ld_b1[h];
        d_params.lo_w1[h][7] = lo_b1[h];
        d_params.g_w1[h][7]  = g_b1[h];
        d_params.w2m[h][7] = 0.f;
        d_params.w2c[h][7] = 0.f;
        d_params.w2g[h][7] = 0.f;
        d_params.cb1[h]   = c_b1[h];
        float v = m_b1[h];                       // h plays the role of j here
        for (int o = 0; o < DOF; o++) v += m_w1[h * 35 + o] * ld_b2[o];
        for (int o = 0; o < 21;  o++) v += m_w1[h * 35 + 7 + o] * lo_b2[o];
        d_params.mb1p[h] = v;
    }
    if (t < 2) { d_params.mb1p[30 + t] = 0.f; d_params.cb1[30 + t] = 0.f; }
    for (int i = t; i < HID * DOF; i += blockDim.x) {
        int h = i / DOF, d = i % DOF;
        d_params.ld_w1[h][d] = ld_w1[i];
        d_params.lo_w1[h][d] = lo_w1[i];
        d_params.g_w1[h][d]  = g_w1[i];
        int j = i / DOF, o = i % DOF;
        d_params.w2m[j][o] = m_w2[o * HID + j];
        d_params.w2c[j][o] = c_w2[o * HID + j];
        d_params.w2g[j][o] = g_w2[o * HID + j];
    }
    for (int i = t; i < DOF * 32; i += blockDim.x) {
        int d = i / 32, j = i % 32;
        d_params.Mq[d][j] = (j < HID) ? m_w1[j * 35 + 28 + d] : 0.f;
        d_params.Cq[d][j] = (j < HID) ? c_w1[j * 203 + 196 + d] : 0.f;
    }
    if (t < 8) d_params.b_out[t] = (t < DOF) ? (m_b2[t] + c_b2[t] + g_b2[t]) : 0.f;
}

// ---------------------------------------------------------------------------
// Prep kernel 2: 8 blocks x 128 threads — one fused-matrix entry per thread
// ---------------------------------------------------------------------------
__global__ void prep_mats(
    const float* __restrict__ ld_w1, const float* __restrict__ ld_w2,
    const float* __restrict__ lo_w1, const float* __restrict__ lo_w2,
    const float* __restrict__ m_w1,  const float* __restrict__ c_w1)
{
    const int i = blockIdx.x * blockDim.x + threadIdx.x;
    if (i >= HID * 32) return;
    const int h = i / 32, j = i % 32;
    if (j >= HID) {
        d_params.MA[h][j] = 0.f; d_params.MB[h][j] = 0.f;
        d_params.CA[h][j] = 0.f; d_params.CB[h][j] = 0.f;
        return;
    }
    float w1ld[DOF], w1lo[DOF];
    #pragma unroll
    for (int d = 0; d < DOF; d++) { w1ld[d] = ld_w1[h * DOF + d]; w1lo[d] = lo_w1[h * DOF + d]; }

    float ma = 0.f, mb = 0.f, ca = 0.f, cb = 0.f;
    #pragma unroll
    for (int o = 0; o < DOF; o++) {
        float w2 = ld_w2[o * HID + h];
        ma += m_w1[j * 35 + o] * w2;
        float s = 0.f;
        #pragma unroll
        for (int d = 0; d < DOF; d++) s += c_w1[j * 203 + o * 7 + d] * w1ld[d];
        ca += w2 * s;
    }
    #pragma unroll
    for (int o = 0; o < 21; o++) {
        float w2 = lo_w2[o * HID + h];
        mb += m_w1[j * 35 + 7 + o] * w2;
        float s = 0.f;
        #pragma unroll
        for (int d = 0; d < DOF; d++) s += c_w1[j * 203 + (7 + o) * 7 + d] * w1lo[d];
        cb += w2 * s;
    }
    d_params.MA[h][j] = ma;
    d_params.MB[h][j] = mb;
    d_params.CA[h][j] = ca;
    d_params.CB[h][j] = cb;
}

// ---------------------------------------------------------------------------
// Packed f32x2 helpers (FFMA2: only reachable via PTX fma.rn.f32x2)
// ---------------------------------------------------------------------------
__device__ __forceinline__ u64 ffma2(u64 a, u64 b, u64 c) {
    u64 d;
    asm("fma.rn.f32x2 %0, %1, %2, %3;" : "=l"(d) : "l"(a), "l"(b), "l"(c));
    return d;
}
__device__ __forceinline__ u64 pk2(float x) {
    u64 r;
    asm("mov.b64 %0, {%1, %2};" : "=l"(r) : "f"(x), "f"(x));
    return r;
}
__device__ __forceinline__ float2 upk(u64 v) {
    float2 f;
    asm("mov.b64 {%0, %1}, %2;" : "=f"(f.x), "=f"(f.y) : "l"(v));
    return f;
}
__device__ __forceinline__ float sigm(float z) {
    return __fdividef(1.f, 1.f + __expf(-z));
}
__device__ __forceinline__ float dot8(const float4 wa, const float4 wb, const float* q) {
    float p = wb.w;                       // bias (q[7]==1 implied)
    p = fmaf(wa.x, q[0], p); p = fmaf(wa.y, q[1], p);
    p = fmaf(wa.z, q[2], p); p = fmaf(wa.w, q[3], p);
    p = fmaf(wb.x, q[4], p); p = fmaf(wb.y, q[5], p);
    p = fmaf(wb.z, q[6], p);
    return p;
}

// z = bias + v @ Mv for two elements (weights loaded once)
__device__ __forceinline__ void vec_init2(const float* __restrict__ bias,
                                          const float (*__restrict__ Mv)[32],
                                          const float* v0, const float* v1,
                                          u64* z0, u64* z1)
{
    const ulonglong2* b = reinterpret_cast<const ulonglong2*>(bias);
    #pragma unroll
    for (int i = 0; i < 8; i++) {
        ulonglong2 w = b[i];
        z0[2*i] = w.x; z0[2*i+1] = w.y;
        z1[2*i] = w.x; z1[2*i+1] = w.y;
    }
    #pragma unroll
    for (int d = 0; d < DOF; d++) {
        u64 a0 = pk2(v0[d]);
        u64 a1 = pk2(v1[d]);
        const ulonglong2* row = reinterpret_cast<const ulonglong2*>(&Mv[d][0]);
        #pragma unroll
        for (int i = 0; i < 8; i++) {
            ulonglong2 w = row[i];
            z0[2*i]   = ffma2(a0, w.x, z0[2*i]);
            z0[2*i+1] = ffma2(a0, w.y, z0[2*i+1]);
            z1[2*i]   = ffma2(a1, w.x, z1[2*i]);
            z1[2*i+1] = ffma2(a1, w.y, z1[2*i+1]);
        }
    }
}

// z += trig(w1 @ [q;1]) @ M for two elements
template <bool COS>
__device__ __forceinline__ void hidden_accum2(const float (*__restrict__ w1)[8],
                                              const float (*__restrict__ M)[32],
                                              const float* q0, const float* q1,
                                              u64* z0, u64* z1)
{
    #pragma unroll 1
    for (int h = 0; h < HID; h++) {
        const float4 wa = *reinterpret_cast<const float4*>(&w1[h][0]);
        const float4 wb = *reinterpret_cast<const float4*>(&w1[h][4]);
        float p0 = dot8(wa, wb, q0);
        float p1 = dot8(wa, wb, q1);
        u64 s0 = pk2(COS ? __cosf(p0) : __sinf(p0));
        u64 s1 = pk2(COS ? __cosf(p1) : __sinf(p1));
        const ulonglong2* row = reinterpret_cast<const ulonglong2*>(&M[h][0]);
        #pragma unroll
        for (int i = 0; i < 8; i++) {
            ulonglong2 w = row[i];
            z0[2*i]   = ffma2(s0, w.x, z0[2*i]);
            z0[2*i+1] = ffma2(s0, w.y, z0[2*i+1]);
            z1[2*i]   = ffma2(s1, w.x, z1[2*i]);
            z1[2*i+1] = ffma2(s1, w.y, z1[2*i+1]);
        }
    }
}

// acc += sigmoid(z) @ w2 for two elements
__device__ __forceinline__ void sig_out2(const u64* z0, const u64* z1,
                                         const float (*__restrict__ w2)[8],
                                         u64* acc0, u64* acc1)
{
    #pragma unroll 1
    for (int p = 0; p < 15; p++) {
        float2 za = upk(z0[p]);
        float2 zb = upk(z1[p]);
        u64 a00 = pk2(sigm(za.x));
        u64 a01 = pk2(sigm(za.y));
        u64 a10 = pk2(sigm(zb.x));
        u64 a11 = pk2(sigm(zb.y));
        const ulonglong2* r0 = reinterpret_cast<const ulonglong2*>(&w2[2*p][0]);
        const ulonglong2* r1 = reinterpret_cast<const ulonglong2*>(&w2[2*p+1][0]);
        ulonglong2 w0a = r0[0], w0b = r0[1];
        ulonglong2 w1a = r1[0], w1b = r1[1];
        acc0[0] = ffma2(a00, w0a.x, acc0[0]); acc0[1] = ffma2(a00, w0a.y, acc0[1]);
        acc0[2] = ffma2(a00, w0b.x, acc0[2]); acc0[3] = ffma2(a00, w0b.y, acc0[3]);
        acc0[0] = ffma2(a01, w1a.x, acc0[0]); acc0[1] = ffma2(a01, w1a.y, acc0[1]);
        acc0[2] = ffma2(a01, w1b.x, acc0[2]); acc0[3] = ffma2(a01, w1b.y, acc0[3]);
        acc1[0] = ffma2(a10, w0a.x, acc1[0]); acc1[1] = ffma2(a10, w0a.y, acc1[1]);
        acc1[2] = ffma2(a10, w0b.x, acc1[2]); acc1[3] = ffma2(a10, w0b.y, acc1[3]);
        acc1[0] = ffma2(a11, w1a.x, acc1[0]); acc1[1] = ffma2(a11, w1a.y, acc1[1]);
        acc1[2] = ffma2(a11, w1b.x, acc1[2]); acc1[3] = ffma2(a11, w1b.y, acc1[3]);
    }
}

// ---------------------------------------------------------------------------
// Main kernel: two batch elements per thread (elements t and t+TPB of block)
// ---------------------------------------------------------------------------
__global__ __launch_bounds__(TPB) void delan_kernel(const float* __restrict__ x,
                                                    float* __restrict__ out, int B)
{
    __shared__ alignas(16) Params sp;
    __shared__ alignas(16) float sx[EPB * 21];   // reused as output staging
    const int t = threadIdx.x;
    const long base = (long)blockIdx.x * EPB;

    // stage fused weights (coalesced float4)
    {
        const float4* src = reinterpret_cast<const float4*>(&d_params);
        float4* dst = reinterpret_cast<float4*>(&sp);
        constexpr int N4 = (int)(sizeof(Params) / 16);
        for (int i = t; i < N4; i += TPB) dst[i] = src[i];
    }
    // stage this block's x rows (coalesced float4)
    {
        const float4* gx = reinterpret_cast<const float4*>(x);
        float4* sx4 = reinterpret_cast<float4*>(sx);
        const long gbase = base * 21 / 4;
        const long gtot  = (long)B * 21 / 4;
        #pragma unroll
        for (int i = t; i < EPB * 21 / 4; i += TPB)
            if (gbase + i < gtot) sx4[i] = gx[gbase + i];
    }
    __syncthreads();

    float q0[8], q1[8];
    #pragma unroll
    for (int d = 0; d < 7; d++) { q0[d] = sx[t * 21 + d]; q1[d] = sx[(t + TPB) * 21 + d]; }
    q0[7] = 1.f; q1[7] = 1.f;

    u64 acc0[4], acc1[4];
    {
        const ulonglong2* b = reinterpret_cast<const ulonglong2*>(sp.b_out);
        ulonglong2 b0 = b[0], b1 = b[1];
        acc0[0] = b0.x; acc0[1] = b0.y; acc0[2] = b1.x; acc0[3] = b1.y;
        acc1[0] = b0.x; acc1[1] = b0.y; acc1[2] = b1.x; acc1[3] = b1.y;
    }

    // ---- g net ------------------------------------------------------------
    #pragma unroll 1
    for (int h = 0; h < HID; h++) {
        const float4 wa = *reinterpret_cast<const float4*>(&sp.g_w1[h][0]);
        const float4 wb = *reinterpret_cast<const float4*>(&sp.g_w1[h][4]);
        u64 s0 = pk2(__sinf(dot8(wa, wb, q0)));
        u64 s1 = pk2(__sinf(dot8(wa, wb, q1)));
        const ulonglong2* r = reinterpret_cast<const ulonglong2*>(&sp.w2g[h][0]);
        ulonglong2 wA = r[0], wB = r[1];
        acc0[0] = ffma2(s0, wA.x, acc0[0]); acc0[1] = ffma2(s0, wA.y, acc0[1]);
        acc0[2] = ffma2(s0, wB.x, acc0[2]); acc0[3] = ffma2(s0, wB.y, acc0[3]);
        acc1[0] = ffma2(s1, wA.x, acc1[0]); acc1[1] = ffma2(s1, wA.y, acc1[1]);
        acc1[2] = ffma2(s1, wB.x, acc1[2]); acc1[3] = ffma2(s1, wB.y, acc1[3]);
    }

    u64 z0[16], z1[16];

    // ---- m head: z = mb1p + qDDot@Mq + sin_ld@MA + sin_lo@MB ---------------
    {
        float v0[7], v1[7];
        #pragma unroll
        for (int d = 0; d < 7; d++) {
            v0[d] = sx[t * 21 + 14 + d];
            v1[d] = sx[(t + TPB) * 21 + 14 + d];
        }
        vec_init2(sp.mb1p, sp.Mq, v0, v1, z0, z1);
    }
    hidden_accum2<false>(sp.ld_w1, sp.MA, q0, q1, z0, z1);
    hidden_accum2<false>(sp.lo_w1, sp.MB, q0, q1, z0, z1);
    sig_out2(z0, z1, sp.w2m, acc0, acc1);

    // ---- c head: z = c_b1 + qDot@Cq + cos_ld@CA + cos_lo@CB ----------------
    {
        float v0[7], v1[7];
        #pragma unroll
        for (int d = 0; d < 7; d++) {
            v0[d] = sx[t * 21 + 7 + d];
            v1[d] = sx[(t + TPB) * 21 + 7 + d];
        }
        vec_init2(sp.cb1, sp.Cq, v0, v1, z0, z1);
    }
    hidden_accum2<true>(sp.ld_w1, sp.CA, q0, q1, z0, z1);
    hidden_accum2<true>(sp.lo_w1, sp.CB, q0, q1, z0, z1);
    sig_out2(z0, z1, sp.w2c, acc0, acc1);

    // ---- output staging (reuse sx) + coalesced store -----------------------
    __syncthreads();                 // all sx reads done before aliasing
    float* so = sx;
    {
        float2 a0 = upk(acc0[0]), a1 = upk(acc0[1]), a2 = upk(acc0[2]), a3 = upk(acc0[3]);
        so[t * 7 + 0] = a0.x; so[t * 7 + 1] = a0.y;
        so[t * 7 + 2] = a1.x; so[t * 7 + 3] = a1.y;
        so[t * 7 + 4] = a2.x; so[t * 7 + 5] = a2.y;
        so[t * 7 + 6] = a3.x;
        float2 b0 = upk(acc1[0]), b1 = upk(acc1[1]), b2 = upk(acc1[2]), b3 = upk(acc1[3]);
        const int u = t + TPB;
        so[u * 7 + 0] = b0.x; so[u * 7 + 1] = b0.y;
        so[u * 7 + 2] = b1.x; so[u * 7 + 3] = b1.y;
        so[u * 7 + 4] = b2.x; so[u * 7 + 5] = b2.y;
        so[u * 7 + 6] = b3.x;
    }
    __syncthreads();
    {
        float4* go = reinterpret_cast<float4*>(out);
        const float4* so4 = reinterpret_cast<const float4*>(so);
        const long obase = base * 7 / 4;
        const long otot  = (long)B * 7 / 4;
        for (int i = t; i < EPB * 7 / 4; i += TPB)
            if (obase + i < otot) go[obase + i] = so4[i];
    }
}

// ---------------------------------------------------------------------------
extern "C" void kernel_launch(void* const* d_in, const int* in_sizes, int n_in,
                              void* d_out, int out_size)
{
    const float* x = (const float*)d_in[0];
    prep_small<<<1, 256>>>(
        (const float*)d_in[1],  (const float*)d_in[2],  (const float*)d_in[3],  (const float*)d_in[4],
        (const float*)d_in[5],  (const float*)d_in[6],  (const float*)d_in[7],  (const float*)d_in[8],
        (const float*)d_in[9],  (const float*)d_in[10], (const float*)d_in[11], (const float*)d_in[12],
        (const float*)d_in[13], (const float*)d_in[14], (const float*)d_in[15], (const float*)d_in[16],
        (const float*)d_in[17], (const float*)d_in[18], (const float*)d_in[19], (const float*)d_in[20]);
    prep_mats<<<8, 128>>>(
        (const float*)d_in[1],  (const float*)d_in[3],
        (const float*)d_in[5],  (const float*)d_in[7],
        (const float*)d_in[13], (const float*)d_in[17]);

    const int B = in_sizes[0] / (3 * DOF);
    const int nb = (B + EPB - 1) / EPB;
    delan_kernel<<<nb, TPB>>>(x, (float*)d_out, B);
}